// round 1
// baseline (speedup 1.0000x reference)
#include <cuda_runtime.h>

// SkelConv: structurally-sparse conv1d over a 25-joint skeleton graph.
// x: (B=32, C_IN=103, T=8192) f32
// w: (C_OUT=206, C_IN=103, K=15) f32 (masked block-tridiagonal)
// bias: (206,), mask: (206,103,15)
// out: (32, 206, 8192) f32
//
// Joint channel blocks: root joint 0 -> 7 in / 14 out channels, joints 1..24 ->
// 4 in / 8 out channels. Out-joint j reads in-joints {j-1, j, j+1} (clamped),
// which is a CONTIGUOUS in-channel range. We exploit that: one CTA per
// (time-tile, joint, batch); only the connected in-channels are traversed.

#define C_IN   103
#define C_OUT  206
#define KK     15
#define TLEN   8192
#define NB     32
#define U      4
#define TPB    128
#define TT     (TPB * U)   // 512 time steps per CTA

__device__ __forceinline__ void joint_params(int j, int& i0, int& iw, int& o0) {
    if (j == 0)       { i0 = 0;              iw = 11; o0 = 0; }
    else if (j == 1)  { i0 = 0;              iw = 15; o0 = 14; }
    else if (j == 24) { i0 = 95;             iw = 8;  o0 = 14 + 23 * 8; }
    else              { i0 = 7 + (j - 2) * 4; iw = 12; o0 = 14 + (j - 1) * 8; }
}

template <int OW>
__global__ void __launch_bounds__(TPB)
skel_conv_kernel(const float* __restrict__ x,
                 const float* __restrict__ w,
                 const float* __restrict__ bias,
                 const float* __restrict__ mask,
                 float* __restrict__ out,
                 int jbase)
{
    const int j = jbase + blockIdx.y;
    int i0, iw, o0;
    joint_params(j, i0, iw, o0);

    const int b   = blockIdx.z;
    const int tid = threadIdx.x;
    const int t0  = blockIdx.x * TT + tid * U;

    // Masked weights for this joint, K padded to 16 for float4 loads.
    __shared__ float wsh[OW][15][16];
    {
        const int total = OW * iw * 16;
        for (int idx = tid; idx < total; idx += TPB) {
            const int k  = idx & 15;
            const int r  = idx >> 4;
            const int ci = r % iw;
            const int co = r / iw;
            float v = 0.0f;
            if (k < KK) {
                const int gi = ((o0 + co) * C_IN + (i0 + ci)) * KK + k;
                v = w[gi] * mask[gi];
            }
            wsh[co][ci][k] = v;
        }
    }
    __syncthreads();

    float acc[OW][U];
#pragma unroll
    for (int co = 0; co < OW; co++)
#pragma unroll
        for (int u = 0; u < U; u++) acc[co][u] = 0.0f;

    const bool interior = (blockIdx.x > 0) && (blockIdx.x + 1 < gridDim.x);
    const float* xb = x + (size_t)b * C_IN * TLEN;

    for (int ci = 0; ci < iw; ci++) {
        const float* xrow = xb + (size_t)(i0 + ci) * TLEN;

        // Sliding window: t in [t0-8, t0+12). FMA uses indices 1..18
        // (x[t0+u+k-7] = xr[u+k+1]).
        float xr[20];
        if (interior) {
            const float4* xq = reinterpret_cast<const float4*>(xrow + t0 - 8);
#pragma unroll
            for (int q = 0; q < 5; q++) {
                const float4 v = xq[q];
                xr[q * 4 + 0] = v.x; xr[q * 4 + 1] = v.y;
                xr[q * 4 + 2] = v.z; xr[q * 4 + 3] = v.w;
            }
        } else {
#pragma unroll
            for (int m = 0; m < 20; m++) {
                const int t = t0 - 8 + m;
                xr[m] = (t >= 0 && t < TLEN) ? xrow[t] : 0.0f;
            }
        }

#pragma unroll
        for (int co = 0; co < OW; co++) {
            float wv[16];
            const float4* wq = reinterpret_cast<const float4*>(&wsh[co][ci][0]);
#pragma unroll
            for (int q = 0; q < 4; q++) {
                const float4 v = wq[q];
                wv[q * 4 + 0] = v.x; wv[q * 4 + 1] = v.y;
                wv[q * 4 + 2] = v.z; wv[q * 4 + 3] = v.w;
            }
#pragma unroll
            for (int k = 0; k < KK; k++) {
#pragma unroll
                for (int u = 0; u < U; u++) {
                    acc[co][u] = fmaf(wv[k], xr[k + u + 1], acc[co][u]);
                }
            }
        }
    }

    float* ob = out + (size_t)b * C_OUT * TLEN + t0;
#pragma unroll
    for (int co = 0; co < OW; co++) {
        const float bv = bias[o0 + co];
        float4 r;
        r.x = acc[co][0] + bv;
        r.y = acc[co][1] + bv;
        r.z = acc[co][2] + bv;
        r.w = acc[co][3] + bv;
        *reinterpret_cast<float4*>(ob + (size_t)(o0 + co) * TLEN) = r;
    }
}

extern "C" void kernel_launch(void* const* d_in, const int* in_sizes, int n_in,
                              void* d_out, int out_size)
{
    (void)in_sizes; (void)n_in; (void)out_size;
    const float* x    = (const float*)d_in[0];
    const float* w    = (const float*)d_in[1];
    const float* bias = (const float*)d_in[2];
    const float* mask = (const float*)d_in[3];
    float* out = (float*)d_out;

    // Root joint (14 out channels)
    dim3 gridA(TLEN / TT, 1, NB);
    skel_conv_kernel<14><<<gridA, TPB>>>(x, w, bias, mask, out, 0);

    // Joints 1..24 (8 out channels each)
    dim3 gridB(TLEN / TT, 24, NB);
    skel_conv_kernel<8><<<gridB, TPB>>>(x, w, bias, mask, out, 1);
}

// round 2
// speedup vs baseline: 1.3638x; 1.3638x over previous
#include <cuda_runtime.h>

// SkelConv via packed fp32x2 FMA (sm_103a FFMA2).
// x: (32, 103, 8192) f32, w: (206, 103, 15) masked block-tridiagonal,
// out: (32, 206, 8192) f32.
//
// One CTA per (time-tile 512, pseudo-joint, batch). 26 pseudo-joints:
// root (14 out ch) split into two 7-wide halves padded to the 8-wide template.
// Weights stored duplicated {w,w} in SMEM so a 64-bit LDS is directly the
// f32x2 multiplier; x sliding window packed into overlapping f32x2 pairs.

#define C_IN   103
#define C_OUT  206
#define KK     15
#define TLEN   8192
#define NB     32
#define U      4
#define TPB    128
#define TT     (TPB * U)   // 512
#define OW     8

__device__ __forceinline__ unsigned long long pack2(float lo, float hi) {
    unsigned long long r;
    asm("mov.b64 %0, {%1, %2};" : "=l"(r) : "f"(lo), "f"(hi));
    return r;
}
__device__ __forceinline__ void unpack2(unsigned long long v, float& lo, float& hi) {
    asm("mov.b64 {%0, %1}, %2;" : "=f"(lo), "=f"(hi) : "l"(v));
}
__device__ __forceinline__ void ffma2(unsigned long long& d,
                                      unsigned long long a,
                                      unsigned long long b) {
    asm("fma.rn.f32x2 %0, %1, %2, %0;" : "+l"(d) : "l"(a), "l"(b));
}

// y = 0..25: 0,1 = root halves (7 out ch each), y>=2 -> joint j=y-1 (8 out ch)
__device__ __forceinline__ void jp(int y, int& i0, int& iw, int& o0, int& ow) {
    if (y == 0)      { i0 = 0;  iw = 11; o0 = 0; ow = 7; }
    else if (y == 1) { i0 = 0;  iw = 11; o0 = 7; ow = 7; }
    else {
        const int j = y - 1;
        o0 = 14 + (j - 1) * 8; ow = 8;
        if (j == 1)       { i0 = 0;              iw = 15; }
        else if (j == 24) { i0 = 95;             iw = 8;  }
        else              { i0 = 7 + (j - 2) * 4; iw = 12; }
    }
}

__global__ void __launch_bounds__(TPB)
skel_conv2_kernel(const float* __restrict__ x,
                  const float* __restrict__ w,
                  const float* __restrict__ bias,
                  const float* __restrict__ mask,
                  float* __restrict__ out)
{
    int i0, iw, o0, ow;
    jp(blockIdx.y, i0, iw, o0, ow);

    const int b   = blockIdx.z;
    const int tid = threadIdx.x;
    const int t0  = blockIdx.x * TT + tid * U;

    // Masked weights, duplicated {w,w}, K padded to 16 pairs for 128-bit LDS.
    __shared__ float2 wsh[OW][15][16];
    {
        const int total = OW * iw * 16;
        for (int idx = tid; idx < total; idx += TPB) {
            const int k  = idx & 15;
            const int r  = idx >> 4;
            const int ci = r % iw;
            const int co = r / iw;
            float v = 0.0f;
            if (k < KK && co < ow) {
                const int gi = ((o0 + co) * C_IN + (i0 + ci)) * KK + k;
                v = w[gi] * mask[gi];
            }
            wsh[co][ci][k] = make_float2(v, v);
        }
    }
    __syncthreads();

    unsigned long long acc01[OW], acc23[OW];
#pragma unroll
    for (int co = 0; co < OW; co++) { acc01[co] = 0ull; acc23[co] = 0ull; }

    const bool interior = (blockIdx.x > 0) && (blockIdx.x + 1 < gridDim.x);
    const float* xb = x + (size_t)b * C_IN * TLEN;

    for (int ci = 0; ci < iw; ci++) {
        const float* xrow = xb + (size_t)(i0 + ci) * TLEN;

        // Window t in [t0-8, t0+12); element m maps to t = t0-8+m.
        float xr[20];
        if (interior) {
            const float4* xq = reinterpret_cast<const float4*>(xrow + t0 - 8);
#pragma unroll
            for (int q = 0; q < 5; q++) {
                const float4 v = xq[q];
                xr[q * 4 + 0] = v.x; xr[q * 4 + 1] = v.y;
                xr[q * 4 + 2] = v.z; xr[q * 4 + 3] = v.w;
            }
        } else {
#pragma unroll
            for (int m = 0; m < 20; m++) {
                const int t = t0 - 8 + m;
                xr[m] = (t >= 0 && t < TLEN) ? xrow[t] : 0.0f;
            }
        }

        // Overlapping pairs: P[m] = {xr[m], xr[m+1]}, m = 1..17.
        unsigned long long P[18];
#pragma unroll
        for (int m = 1; m <= 17; m++) P[m] = pack2(xr[m], xr[m + 1]);

#pragma unroll
        for (int co = 0; co < OW; co++) {
            const ulonglong2* wq =
                reinterpret_cast<const ulonglong2*>(&wsh[co][ci][0]);
#pragma unroll
            for (int q = 0; q < 8; q++) {
                const ulonglong2 v = wq[q];
                const int k0 = 2 * q;
                ffma2(acc01[co], v.x, P[k0 + 1]);
                ffma2(acc23[co], v.x, P[k0 + 3]);
                if (k0 + 1 < KK) {
                    ffma2(acc01[co], v.y, P[k0 + 2]);
                    ffma2(acc23[co], v.y, P[k0 + 4]);
                }
            }
        }
    }

    float* ob = out + (size_t)b * C_OUT * TLEN + t0;
#pragma unroll
    for (int co = 0; co < OW; co++) {
        if (co < ow) {
            const float bv = bias[o0 + co];
            float4 r;
            unpack2(acc01[co], r.x, r.y);
            unpack2(acc23[co], r.z, r.w);
            r.x += bv; r.y += bv; r.z += bv; r.w += bv;
            *reinterpret_cast<float4*>(ob + (size_t)(o0 + co) * TLEN) = r;
        }
    }
}

extern "C" void kernel_launch(void* const* d_in, const int* in_sizes, int n_in,
                              void* d_out, int out_size)
{
    (void)in_sizes; (void)n_in; (void)out_size;
    const float* x    = (const float*)d_in[0];
    const float* w    = (const float*)d_in[1];
    const float* bias = (const float*)d_in[2];
    const float* mask = (const float*)d_in[3];
    float* out = (float*)d_out;

    dim3 grid(TLEN / TT, 26, NB);
    skel_conv2_kernel<<<grid, TPB>>>(x, w, bias, mask, out);
}